// round 3
// baseline (speedup 1.0000x reference)
#include <cuda_runtime.h>
#include <math.h>
#include <float.h>

#define B_   8
#define CIN  32
#define CI   16
#define Hh   128
#define Ww   128
#define NHH  31
#define LL   961
#define FIN  784
#define FOUT 196
#define FV   1568
#define NTHREADS 256

// ---------------- scratch (device globals; no cudaMalloc allowed) -------------
__device__ float g_x1[(size_t)B_*CI*Hh*Ww];
__device__ float g_x2[(size_t)B_*CI*Hh*Ww];
__device__ float g_x3[(size_t)B_*CIN*Hh*Ww];
__device__ float g_p6[(size_t)B_*LL*FIN];
__device__ float g_p4[(size_t)B_*LL*FIN];
__device__ float g_p62[(size_t)B_*LL*FV];
__device__ float g_wf[(size_t)B_*LL*FOUT];
__device__ float g_xf[(size_t)B_*LL*FOUT];
__device__ float g_A[(size_t)B_*LL*LL];
__device__ float g_Ti[(size_t)B_*LL*LL];
__device__ float g_Msum[(size_t)LL*LL];
__device__ float g_bsum[LL];
__device__ float g_y[(size_t)B_*LL*FV];
__device__ float g_fold[(size_t)B_*CIN*Hh*Ww];
__device__ float g_o1[(size_t)B_*CI*Hh*Ww];

// Stable logistic with FTZ-underflow zero semantics:
// returns exactly 0 iff expf(x) < FLT_MIN (x < ln(2^-126) ~= -87.3365),
// matching the reference's masked-zero cutoff inferred from error analysis.
static __device__ __forceinline__ float sigmoid_ref(float x) {
    if (x >= 0.f) return 1.f / (1.f + expf(-x));
    float e = expf(x);
    if (e < FLT_MIN) e = 0.f;         // flush denormals -> exact zero
    return e / (1.f + e);
}

// ---------------- conv: refpad 3x3, 32->16 twice (x1, x2) --------------------
__global__ void conv3x3_dual_kernel(const float* __restrict__ x,
                                    const float* __restrict__ w1, const float* __restrict__ b1,
                                    const float* __restrict__ w2, const float* __restrict__ b2)
{
    __shared__ float sw1[CI*CIN*9];
    __shared__ float sw2[CI*CIN*9];
    int t = threadIdx.x;
    for (int i = t; i < CI*CIN*9; i += NTHREADS) { sw1[i] = w1[i]; sw2[i] = w2[i]; }
    __syncthreads();
    int pix = blockIdx.x * NTHREADS + t;
    int b = blockIdx.y;
    int h = pix >> 7, w = pix & 127;
    float acc1[CI], acc2[CI];
    #pragma unroll
    for (int co = 0; co < CI; co++) { acc1[co] = b1[co]; acc2[co] = b2[co]; }
    const float* xb = x + (size_t)b * CIN * Hh * Ww;
    for (int ci = 0; ci < CIN; ci++) {
        float v[9];
        #pragma unroll
        for (int dh = 0; dh < 3; dh++) {
            int hh = h + dh - 1;
            hh = hh < 0 ? 1 : (hh >= Hh ? Hh - 2 : hh);   // reflect pad=1
            #pragma unroll
            for (int dw = 0; dw < 3; dw++) {
                int w2p = w + dw - 1;
                w2p = w2p < 0 ? 1 : (w2p >= Ww ? Ww - 2 : w2p);
                v[dh*3 + dw] = xb[(ci*Hh + hh)*Ww + w2p];
            }
        }
        #pragma unroll
        for (int co = 0; co < CI; co++) {
            const float* p1 = &sw1[(co*CIN + ci)*9];
            const float* p2 = &sw2[(co*CIN + ci)*9];
            float s1 = 0.f, s2 = 0.f;
            #pragma unroll
            for (int k = 0; k < 9; k++) { s1 += p1[k]*v[k]; s2 += p2[k]*v[k]; }
            acc1[co] += s1; acc2[co] += s2;
        }
    }
    size_t base = (size_t)b * CI * Hh * Ww + pix;
    #pragma unroll
    for (int co = 0; co < CI; co++) {
        g_x1[base + (size_t)co*Hh*Ww] = acc1[co];
        g_x2[base + (size_t)co*Hh*Ww] = acc2[co];
    }
}

// ---------------- conv: 1x1 theta, x1(16) -> x3(32), +bias -------------------
__global__ void conv1x1_theta_kernel(const float* __restrict__ tw, const float* __restrict__ tb)
{
    __shared__ float sw[CIN*CI];
    int t = threadIdx.x;
    for (int i = t; i < CIN*CI; i += NTHREADS) sw[i] = tw[i];
    __syncthreads();
    int pix = blockIdx.x * NTHREADS + t;
    int b = blockIdx.y;
    float in[CI];
    #pragma unroll
    for (int ci = 0; ci < CI; ci++) in[ci] = g_x1[((size_t)b*CI + ci)*Hh*Ww + pix];
    #pragma unroll
    for (int co = 0; co < CIN; co++) {
        float s = tb[co];
        #pragma unroll
        for (int ci = 0; ci < CI; ci++) s += sw[co*CI + ci]*in[ci];
        g_x3[((size_t)b*CIN + co)*Hh*Ww + pix] = s;
    }
}

// ---------------- unfold (patch gather): src(B,C,H,W) -> dst(B,L,C*49) -------
__global__ void unfold_kernel(const float* __restrict__ src, float* __restrict__ dst,
                              int C, size_t total)
{
    size_t t = (size_t)blockIdx.x * NTHREADS + threadIdx.x;
    if (t >= total) return;
    int F = C * 49;
    int f = (int)(t % F);
    size_t r = t / F;
    int l = (int)(r % LL);
    int b = (int)(r / LL);
    int c = f / 49, rr = f % 49, kh = rr / 7, kw = rr % 7;
    int h = (l / NHH)*4 + kh, w = (l % NHH)*4 + kw;
    dst[t] = src[(((size_t)b*C + c)*Hh + h)*Ww + w];
}

// ---------------- Msum = mconv_w + mfc_w, bsum = mconv_b + mfc_b -------------
__global__ void msum_kernel(const float* __restrict__ mw1, const float* __restrict__ mw2,
                            const float* __restrict__ mb1, const float* __restrict__ mb2)
{
    size_t t = (size_t)blockIdx.x * NTHREADS + threadIdx.x;
    if (t < (size_t)LL*LL) g_Msum[t] = mw1[t] + mw2[t];
    if (t < LL) g_bsum[t] = mb1[t] + mb2[t];
}

// ---------------- tiled SGEMM: C = A @ op(B) (+rowBias +colBias) -------------
// BT=true : B stored (N,K) row-major  -> C[m,n] = sum_k A[m,k]*B[n,k]
// BT=false: B stored (K,N) row-major  -> C[m,n] = sum_k A[m,k]*B[k,n]
template <bool BT>
__global__ void gemm_kernel(const float* __restrict__ Ag, const float* __restrict__ Bg,
                            float* __restrict__ Cg, int M, int N, int K,
                            long long sA, long long sB, long long sC,
                            const float* __restrict__ rowBias,
                            const float* __restrict__ colBias)
{
    __shared__ float As[16][68];
    __shared__ float Bs[16][68];
    int tid = threadIdx.x;
    int tx = tid & 15, ty = tid >> 4;
    int m0 = blockIdx.y * 64, n0 = blockIdx.x * 64;
    const float* Ab = Ag + (long long)blockIdx.z * sA;
    const float* Bb = Bg + (long long)blockIdx.z * sB;
    float*       Cb = Cg + (long long)blockIdx.z * sC;
    float acc[4][4];
    #pragma unroll
    for (int i = 0; i < 4; i++)
        #pragma unroll
        for (int j = 0; j < 4; j++) acc[i][j] = 0.f;

    for (int k0 = 0; k0 < K; k0 += 16) {
        {
            int kk = tid & 15, rb = tid >> 4;
            #pragma unroll
            for (int i = 0; i < 4; i++) {
                int r = rb*4 + i;
                int gm = m0 + r, gk = k0 + kk;
                As[kk][r] = (gm < M && gk < K) ? Ab[(long long)gm*K + gk] : 0.f;
            }
        }
        if (BT) {
            int kk = tid & 15, rb = tid >> 4;
            #pragma unroll
            for (int i = 0; i < 4; i++) {
                int n = rb*4 + i;
                int gn = n0 + n, gk = k0 + kk;
                Bs[kk][n] = (gn < N && gk < K) ? Bb[(long long)gn*K + gk] : 0.f;
            }
        } else {
            int nn = tid & 63, kb = tid >> 6;
            #pragma unroll
            for (int i = 0; i < 4; i++) {
                int kk = kb*4 + i;
                int gn = n0 + nn, gk = k0 + kk;
                Bs[kk][nn] = (gn < N && gk < K) ? Bb[(long long)gk*N + gn] : 0.f;
            }
        }
        __syncthreads();
        #pragma unroll
        for (int kk = 0; kk < 16; kk++) {
            float a[4], bv[4];
            #pragma unroll
            for (int i = 0; i < 4; i++) a[i] = As[kk][ty*4 + i];
            #pragma unroll
            for (int j = 0; j < 4; j++) bv[j] = Bs[kk][tx*4 + j];
            #pragma unroll
            for (int i = 0; i < 4; i++)
                #pragma unroll
                for (int j = 0; j < 4; j++) acc[i][j] += a[i]*bv[j];
        }
        __syncthreads();
    }
    #pragma unroll
    for (int i = 0; i < 4; i++) {
        int gm = m0 + ty*4 + i;
        if (gm >= M) continue;
        float rbv = rowBias ? rowBias[gm] : 0.f;
        #pragma unroll
        for (int j = 0; j < 4; j++) {
            int gn = n0 + tx*4 + j;
            if (gn < N) {
                float v = acc[i][j] + rbv;
                if (colBias) v += colBias[gn];
                Cb[(long long)gm*N + gn] = v;
            }
        }
    }
}

// ---------------- masked softmax row kernel -> Am (into d_out) ---------------
__global__ void softmax_kernel(float* __restrict__ Am)
{
    int row = blockIdx.x;                    // b*L + l
    const float* Ar = g_A  + (size_t)row * LL;
    const float* Tr = g_Ti + (size_t)row * LL;
    int t = threadIdx.x;
    const float scale = 0.07142857142857142f;   // 196^-0.5
    float v[4], mb[4];
    float mx = -INFINITY;
    #pragma unroll
    for (int i = 0; i < 4; i++) {
        int m = t + i*NTHREADS;
        v[i] = 0.f; mb[i] = 0.f;
        if (m < LL) {
            float mask = sigmoid_ref(Tr[m]);
            v[i] = Ar[m] * mask * scale;
            mb[i] = (mask != 0.f) ? 1.f : 0.f;
            mx = fmaxf(mx, v[i]);
        }
    }
    __shared__ float red[NTHREADS];
    red[t] = mx; __syncthreads();
    for (int s = NTHREADS/2; s > 0; s >>= 1) {
        if (t < s) red[t] = fmaxf(red[t], red[t+s]);
        __syncthreads();
    }
    mx = red[0]; __syncthreads();
    float e[4]; float sum = 0.f;
    #pragma unroll
    for (int i = 0; i < 4; i++) {
        int m = t + i*NTHREADS;
        if (m < LL) { e[i] = expf(v[i] - mx); sum += e[i]; } else e[i] = 0.f;
    }
    red[t] = sum; __syncthreads();
    for (int s = NTHREADS/2; s > 0; s >>= 1) {
        if (t < s) red[t] += red[t+s];
        __syncthreads();
    }
    float inv = 1.f / red[0];
    #pragma unroll
    for (int i = 0; i < 4; i++) {
        int m = t + i*NTHREADS;
        if (m < LL) Am[(size_t)row*LL + m] = e[i] * inv * mb[i];
    }
}

// ---------------- fold (gather form, no atomics) ------------------------------
__global__ void fold_kernel()
{
    size_t t = (size_t)blockIdx.x * NTHREADS + threadIdx.x;
    if (t >= (size_t)B_*CIN*Hh*Ww) return;
    int w = (int)(t % Ww); size_t r = t / Ww;
    int h = (int)(r % Hh); r /= Hh;
    int c = (int)(r % CIN);
    int b = (int)(r / CIN);
    int i0 = (h > 6) ? (h - 3) >> 2 : 0;         // ceil((h-6)/4)
    int i1 = h >> 2; if (i1 > NHH - 1) i1 = NHH - 1;
    int j0 = (w > 6) ? (w - 3) >> 2 : 0;
    int j1 = w >> 2; if (j1 > NHH - 1) j1 = NHH - 1;
    float s = 0.f;
    for (int i = i0; i <= i1; i++) {
        int kh = h - i*4;
        for (int j = j0; j <= j1; j++) {
            int kw = w - j*4;
            s += g_y[((size_t)b*LL + i*NHH + j)*FV + c*49 + kh*7 + kw];
        }
    }
    g_fold[t] = s;
}

// ---------------- conv c1: refpad 3x3, 32->16, leaky(0.2) --------------------
__global__ void conv3x3_c1_kernel(const float* __restrict__ w1)
{
    __shared__ float sw[CI*CIN*9];
    int t = threadIdx.x;
    for (int i = t; i < CI*CIN*9; i += NTHREADS) sw[i] = w1[i];
    __syncthreads();
    int pix = blockIdx.x * NTHREADS + t;
    int b = blockIdx.y;
    int h = pix >> 7, w = pix & 127;
    float acc[CI];
    #pragma unroll
    for (int co = 0; co < CI; co++) acc[co] = 0.f;
    const float* xb = g_fold + (size_t)b * CIN * Hh * Ww;
    for (int ci = 0; ci < CIN; ci++) {
        float v[9];
        #pragma unroll
        for (int dh = 0; dh < 3; dh++) {
            int hh = h + dh - 1;
            hh = hh < 0 ? 1 : (hh >= Hh ? Hh - 2 : hh);
            #pragma unroll
            for (int dw = 0; dw < 3; dw++) {
                int w2p = w + dw - 1;
                w2p = w2p < 0 ? 1 : (w2p >= Ww ? Ww - 2 : w2p);
                v[dh*3 + dw] = xb[(ci*Hh + hh)*Ww + w2p];
            }
        }
        #pragma unroll
        for (int co = 0; co < CI; co++) {
            const float* p1 = &sw[(co*CIN + ci)*9];
            float s1 = 0.f;
            #pragma unroll
            for (int k = 0; k < 9; k++) s1 += p1[k]*v[k];
            acc[co] += s1;
        }
    }
    size_t base = (size_t)b * CI * Hh * Ww + pix;
    #pragma unroll
    for (int co = 0; co < CI; co++) {
        float s = acc[co];
        g_o1[base + (size_t)co*Hh*Ww] = (s > 0.f) ? s : 0.2f*s;
    }
}

// ---------------- conv c2: 1x1 16->32, leaky(0.2), + residual ----------------
__global__ void conv1x1_c2_res_kernel(const float* __restrict__ cw,
                                      const float* __restrict__ x,
                                      float* __restrict__ outp)
{
    __shared__ float sw[CIN*CI];
    int t = threadIdx.x;
    for (int i = t; i < CIN*CI; i += NTHREADS) sw[i] = cw[i];
    __syncthreads();
    int pix = blockIdx.x * NTHREADS + t;
    int b = blockIdx.y;
    float in[CI];
    #pragma unroll
    for (int ci = 0; ci < CI; ci++) in[ci] = g_o1[((size_t)b*CI + ci)*Hh*Ww + pix];
    #pragma unroll
    for (int co = 0; co < CIN; co++) {
        float s = 0.f;
        #pragma unroll
        for (int ci = 0; ci < CI; ci++) s += sw[co*CI + ci]*in[ci];
        s = (s > 0.f) ? s : 0.2f*s;
        size_t idx = ((size_t)b*CIN + co)*Hh*Ww + pix;
        outp[idx] = x[idx] + s;
    }
}

// ---------------- launch ------------------------------------------------------
extern "C" void kernel_launch(void* const* d_in, const int* in_sizes, int n_in,
                              void* d_out, int out_size)
{
    const float* x        = (const float*)d_in[0];
    const float* g_w      = (const float*)d_in[1];
    const float* g_b      = (const float*)d_in[2];
    const float* w_w      = (const float*)d_in[3];
    const float* w_b      = (const float*)d_in[4];
    const float* theta_w  = (const float*)d_in[5];
    const float* theta_b  = (const float*)d_in[6];
    const float* fc1_w    = (const float*)d_in[7];
    const float* fc1_b    = (const float*)d_in[8];
    const float* mconv_w  = (const float*)d_in[9];
    const float* mconv_b  = (const float*)d_in[10];
    const float* mfc_w    = (const float*)d_in[11];
    const float* mfc_b    = (const float*)d_in[12];
    const float* c1_w     = (const float*)d_in[13];
    const float* c2_w     = (const float*)d_in[14];
    float* out = (float*)d_out;

    float *px1, *px2, *px3, *pp6, *pp4, *pp62, *pwf, *pxf, *pA, *pTi, *pMsum, *pbsum, *py;
    cudaGetSymbolAddress((void**)&px1,  g_x1);
    cudaGetSymbolAddress((void**)&px2,  g_x2);
    cudaGetSymbolAddress((void**)&px3,  g_x3);
    cudaGetSymbolAddress((void**)&pp6,  g_p6);
    cudaGetSymbolAddress((void**)&pp4,  g_p4);
    cudaGetSymbolAddress((void**)&pp62, g_p62);
    cudaGetSymbolAddress((void**)&pwf,  g_wf);
    cudaGetSymbolAddress((void**)&pxf,  g_xf);
    cudaGetSymbolAddress((void**)&pA,   g_A);
    cudaGetSymbolAddress((void**)&pTi,  g_Ti);
    cudaGetSymbolAddress((void**)&pMsum,g_Msum);
    cudaGetSymbolAddress((void**)&pbsum,g_bsum);
    cudaGetSymbolAddress((void**)&py,   g_y);

    dim3 convGrid(Hh*Ww/NTHREADS, B_);

    // x1, x2 (refpad conv3x3) ; x3 = theta(x1)
    conv3x3_dual_kernel<<<convGrid, NTHREADS>>>(x, g_w, g_b, w_w, w_b);
    conv1x1_theta_kernel<<<convGrid, NTHREADS>>>(theta_w, theta_b);

    // unfolds
    {
        size_t tot = (size_t)B_*LL*FIN;
        int nb = (int)((tot + NTHREADS - 1) / NTHREADS);
        unfold_kernel<<<nb, NTHREADS>>>(px1, pp6,  CI, tot);
        unfold_kernel<<<nb, NTHREADS>>>(px2, pp4,  CI, tot);
    }
    {
        size_t tot = (size_t)B_*LL*FV;
        int nb = (int)((tot + NTHREADS - 1) / NTHREADS);
        unfold_kernel<<<nb, NTHREADS>>>(px3, pp62, CIN, tot);
    }

    // Msum / bsum
    msum_kernel<<<(int)(((size_t)LL*LL + NTHREADS - 1)/NTHREADS), NTHREADS>>>(
        mconv_w, mfc_w, mconv_b, mfc_b);

    // wf = p4 @ fc1_w^T + fc1_b ; xf = p6 @ fc1_w^T + fc1_b   (flat M = B*L)
    {
        dim3 g((FOUT + 63)/64, (B_*LL + 63)/64, 1);
        gemm_kernel<true><<<g, NTHREADS>>>(pp4, fc1_w, pwf, B_*LL, FOUT, FIN,
                                           0, 0, 0, nullptr, fc1_b);
        gemm_kernel<true><<<g, NTHREADS>>>(pp6, fc1_w, pxf, B_*LL, FOUT, FIN,
                                           0, 0, 0, nullptr, fc1_b);
    }

    // A[b] = wf[b] @ xf[b]^T ; Ti[b] = Msum @ A[b] + bsum
    {
        dim3 g((LL + 63)/64, (LL + 63)/64, B_);
        gemm_kernel<true><<<g, NTHREADS>>>(pwf, pxf, pA, LL, LL, FOUT,
                                           (long long)LL*FOUT, (long long)LL*FOUT,
                                           (long long)LL*LL, nullptr, nullptr);
        gemm_kernel<false><<<g, NTHREADS>>>(pMsum, pA, pTi, LL, LL, LL,
                                            0, (long long)LL*LL,
                                            (long long)LL*LL, pbsum, nullptr);
    }

    // Am -> d_out[0 : B*L*L)
    softmax_kernel<<<B_*LL, NTHREADS>>>(out);

    // y[b] = Am[b] @ p62[b]
    {
        dim3 g((FV + 63)/64, (LL + 63)/64, B_);
        gemm_kernel<false><<<g, NTHREADS>>>(out, pp62, py, LL, FV, LL,
                                            (long long)LL*LL, (long long)LL*FV,
                                            (long long)LL*FV, nullptr, nullptr);
    }

    // fold -> conv c1 (lrelu) -> conv c2 (lrelu) + residual -> d_out tail
    fold_kernel<<<(int)(((size_t)B_*CIN*Hh*Ww + NTHREADS - 1)/NTHREADS), NTHREADS>>>();
    conv3x3_c1_kernel<<<convGrid, NTHREADS>>>(c1_w);
    conv1x1_c2_res_kernel<<<convGrid, NTHREADS>>>(c2_w, x, out + (size_t)B_*LL*LL);
}

// round 4
// speedup vs baseline: 1.4155x; 1.4155x over previous
#include <cuda_runtime.h>
#include <math.h>
#include <float.h>

#define B_   8
#define CIN  32
#define CI   16
#define Hh   128
#define Ww   128
#define NHH  31
#define LL   961
#define LLP  964      // padded row stride (%4==0)
#define FIN  784
#define FOUT 196
#define FV   1568
#define NTHREADS 256

// ---------------- scratch (device globals; no cudaMalloc allowed) -------------
__device__ float g_x1[(size_t)B_*CI*Hh*Ww];
__device__ float g_x2[(size_t)B_*CI*Hh*Ww];
__device__ float g_x3[(size_t)B_*CIN*Hh*Ww];
__device__ float g_p6[(size_t)B_*LL*FIN];
__device__ float g_p4[(size_t)B_*LL*FIN];
__device__ float g_p62[(size_t)B_*LL*FV];
__device__ float g_wf[(size_t)B_*LL*FOUT];
__device__ float g_xf[(size_t)B_*LL*FOUT];
__device__ float g_A[(size_t)B_*LL*LL];
__device__ float g_Ti[(size_t)B_*LL*LL];
__device__ float g_W2[(size_t)B_*LL*FOUT];
__device__ float g_MsumP[(size_t)LL*LLP];
__device__ float g_bsum[LL];
__device__ float g_AmP[(size_t)B_*LL*LLP];
__device__ float g_y[(size_t)B_*LL*FV];
__device__ float g_fold[(size_t)B_*CIN*Hh*Ww];
__device__ float g_o1[(size_t)B_*CI*Hh*Ww];

// Stable logistic, zero iff expf(x) < FLT_MIN (x < ~-87.3365) — matches ref.
static __device__ __forceinline__ float sigmoid_ref(float x) {
    if (x >= 0.f) return 1.f / (1.f + expf(-x));
    float e = expf(x);
    if (e < FLT_MIN) e = 0.f;
    return e / (1.f + e);
}

// ---------------- conv: refpad 3x3, 32->16 twice (x1, x2) --------------------
__global__ void conv3x3_dual_kernel(const float* __restrict__ x,
                                    const float* __restrict__ w1, const float* __restrict__ b1,
                                    const float* __restrict__ w2, const float* __restrict__ b2)
{
    __shared__ float sw1[CI*CIN*9];
    __shared__ float sw2[CI*CIN*9];
    int t = threadIdx.x;
    for (int i = t; i < CI*CIN*9; i += NTHREADS) { sw1[i] = w1[i]; sw2[i] = w2[i]; }
    __syncthreads();
    int pix = blockIdx.x * NTHREADS + t;
    int b = blockIdx.y;
    int h = pix >> 7, w = pix & 127;
    float acc1[CI], acc2[CI];
    #pragma unroll
    for (int co = 0; co < CI; co++) { acc1[co] = b1[co]; acc2[co] = b2[co]; }
    const float* xb = x + (size_t)b * CIN * Hh * Ww;
    for (int ci = 0; ci < CIN; ci++) {
        float v[9];
        #pragma unroll
        for (int dh = 0; dh < 3; dh++) {
            int hh = h + dh - 1;
            hh = hh < 0 ? 1 : (hh >= Hh ? Hh - 2 : hh);
            #pragma unroll
            for (int dw = 0; dw < 3; dw++) {
                int w2p = w + dw - 1;
                w2p = w2p < 0 ? 1 : (w2p >= Ww ? Ww - 2 : w2p);
                v[dh*3 + dw] = xb[(ci*Hh + hh)*Ww + w2p];
            }
        }
        #pragma unroll
        for (int co = 0; co < CI; co++) {
            const float* p1 = &sw1[(co*CIN + ci)*9];
            const float* p2 = &sw2[(co*CIN + ci)*9];
            float s1 = 0.f, s2 = 0.f;
            #pragma unroll
            for (int k = 0; k < 9; k++) { s1 += p1[k]*v[k]; s2 += p2[k]*v[k]; }
            acc1[co] += s1; acc2[co] += s2;
        }
    }
    size_t base = (size_t)b * CI * Hh * Ww + pix;
    #pragma unroll
    for (int co = 0; co < CI; co++) {
        g_x1[base + (size_t)co*Hh*Ww] = acc1[co];
        g_x2[base + (size_t)co*Hh*Ww] = acc2[co];
    }
}

// ---------------- conv: 1x1 theta, x1(16) -> x3(32), +bias -------------------
__global__ void conv1x1_theta_kernel(const float* __restrict__ tw, const float* __restrict__ tb)
{
    __shared__ float sw[CIN*CI];
    int t = threadIdx.x;
    for (int i = t; i < CIN*CI; i += NTHREADS) sw[i] = tw[i];
    __syncthreads();
    int pix = blockIdx.x * NTHREADS + t;
    int b = blockIdx.y;
    float in[CI];
    #pragma unroll
    for (int ci = 0; ci < CI; ci++) in[ci] = g_x1[((size_t)b*CI + ci)*Hh*Ww + pix];
    #pragma unroll
    for (int co = 0; co < CIN; co++) {
        float s = tb[co];
        #pragma unroll
        for (int ci = 0; ci < CI; ci++) s += sw[co*CI + ci]*in[ci];
        g_x3[((size_t)b*CIN + co)*Hh*Ww + pix] = s;
    }
}

// ---------------- unfold: src(B,C,H,W) -> dst(B,L,C*49) ----------------------
__global__ void unfold_kernel(const float* __restrict__ src, float* __restrict__ dst,
                              int C, size_t total)
{
    size_t t = (size_t)blockIdx.x * NTHREADS + threadIdx.x;
    if (t >= total) return;
    int F = C * 49;
    int f = (int)(t % F);
    size_t r = t / F;
    int l = (int)(r % LL);
    int b = (int)(r / LL);
    int c = f / 49, rr = f % 49, kh = rr / 7, kw = rr % 7;
    int h = (l / NHH)*4 + kh, w = (l % NHH)*4 + kw;
    dst[t] = src[(((size_t)b*C + c)*Hh + h)*Ww + w];
}

// ---------------- MsumP (stride 964) = mconv_w + mfc_w; bsum -----------------
__global__ void msum_kernel(const float* __restrict__ mw1, const float* __restrict__ mw2,
                            const float* __restrict__ mb1, const float* __restrict__ mb2)
{
    size_t t = (size_t)blockIdx.x * NTHREADS + threadIdx.x;
    if (t < (size_t)LL*LL) {
        int n = (int)(t / LL), c = (int)(t % LL);
        g_MsumP[(size_t)n*LLP + c] = mw1[t] + mw2[t];
    }
    if (t < LL) g_bsum[t] = mb1[t] + mb2[t];
}

// ============ fp32 SGEMM: 128x128x16, 8x8/thread, float4 =====================
// BT=true : B stored (N,K) row-major  -> C[m,n] = sum_k A[m,k]*B[n,k]
// BT=false: B stored (K,N) row-major  -> C[m,n] = sum_k A[m,k]*B[k,n]
template <bool BT>
__global__ void __launch_bounds__(256, 2) gemm128_kernel(
    const float* __restrict__ Ag, const float* __restrict__ Bg,
    float* __restrict__ Cg, int M, int N, int K,
    int lda, int ldb, int ldc,
    long long sA, long long sB, long long sC,
    const float* __restrict__ rowBias, const float* __restrict__ colBias)
{
    __shared__ float As[16][132];
    __shared__ float Bs[16][132];
    const int tid = threadIdx.x;
    const int tx = tid & 15, ty = tid >> 4;
    const int m0 = blockIdx.y * 128, n0 = blockIdx.x * 128;
    const float* Ab = Ag + (long long)blockIdx.z * sA;
    const float* Bb = Bg + (long long)blockIdx.z * sB;
    float*       Cb = Cg + (long long)blockIdx.z * sC;

    float acc[8][8];
    #pragma unroll
    for (int i = 0; i < 8; i++)
        #pragma unroll
        for (int j = 0; j < 8; j++) acc[i][j] = 0.f;

    const int a_c = (tid & 3) * 4;   // k offset within chunk
    const int a_r = tid >> 2;        // 0..63
    const int bn_q = (tid & 31) * 4; // n offset (BT=false)
    const int bk_r = tid >> 5;       // 0..7

    for (int k0 = 0; k0 < K; k0 += 16) {
        const bool fullk = (k0 + 16 <= K);
        // A tile -> As[k][m]
        #pragma unroll
        for (int i = 0; i < 2; i++) {
            int m = a_r + 64*i;
            int gm = m0 + m;
            float4 v = make_float4(0.f,0.f,0.f,0.f);
            if (gm < M) {
                const float* p = Ab + (long long)gm*lda + k0 + a_c;
                if (fullk) v = *(const float4*)p;
                else {
                    if (k0 + a_c + 0 < K) v.x = p[0];
                    if (k0 + a_c + 1 < K) v.y = p[1];
                    if (k0 + a_c + 2 < K) v.z = p[2];
                    if (k0 + a_c + 3 < K) v.w = p[3];
                }
            }
            As[a_c+0][m] = v.x; As[a_c+1][m] = v.y;
            As[a_c+2][m] = v.z; As[a_c+3][m] = v.w;
        }
        // B tile -> Bs[k][n]
        if (BT) {
            #pragma unroll
            for (int i = 0; i < 2; i++) {
                int n = a_r + 64*i;
                int gn = n0 + n;
                float4 v = make_float4(0.f,0.f,0.f,0.f);
                if (gn < N) {
                    const float* p = Bb + (long long)gn*ldb + k0 + a_c;
                    if (fullk) v = *(const float4*)p;
                    else {
                        if (k0 + a_c + 0 < K) v.x = p[0];
                        if (k0 + a_c + 1 < K) v.y = p[1];
                        if (k0 + a_c + 2 < K) v.z = p[2];
                        if (k0 + a_c + 3 < K) v.w = p[3];
                    }
                }
                Bs[a_c+0][n] = v.x; Bs[a_c+1][n] = v.y;
                Bs[a_c+2][n] = v.z; Bs[a_c+3][n] = v.w;
            }
        } else {
            #pragma unroll
            for (int i = 0; i < 2; i++) {
                int k = bk_r + 8*i;
                int gk = k0 + k;
                int gn = n0 + bn_q;
                float4 v = make_float4(0.f,0.f,0.f,0.f);
                if (gk < K) {
                    const float* p = Bb + (long long)gk*ldb + gn;
                    if (gn + 3 < N) v = *(const float4*)p;
                    else {
                        if (gn+0 < N) v.x = p[0];
                        if (gn+1 < N) v.y = p[1];
                        if (gn+2 < N) v.z = p[2];
                    }
                }
                *(float4*)&Bs[k][bn_q] = v;
            }
        }
        __syncthreads();
        #pragma unroll
        for (int k = 0; k < 16; k++) {
            float a[8], b[8];
            *(float4*)&a[0] = *(const float4*)&As[k][ty*8];
            *(float4*)&a[4] = *(const float4*)&As[k][ty*8+4];
            *(float4*)&b[0] = *(const float4*)&Bs[k][tx*8];
            *(float4*)&b[4] = *(const float4*)&Bs[k][tx*8+4];
            #pragma unroll
            for (int i = 0; i < 8; i++)
                #pragma unroll
                for (int j = 0; j < 8; j++) acc[i][j] += a[i]*b[j];
        }
        __syncthreads();
    }
    #pragma unroll
    for (int i = 0; i < 8; i++) {
        int gm = m0 + ty*8 + i;
        if (gm >= M) continue;
        float rb = rowBias ? rowBias[gm] : 0.f;
        #pragma unroll
        for (int j = 0; j < 8; j++) {
            int gn = n0 + tx*8 + j;
            if (gn < N) {
                float v = acc[i][j] + rb;
                if (colBias) v += colBias[gn];
                Cb[(long long)gm*ldc + gn] = v;
            }
        }
    }
}

// ============ TF32 tensor-core GEMM (y = Am @ p62 only) =======================
__device__ __forceinline__ unsigned f2tf32(float x) {
    unsigned r;
    asm("cvt.rna.tf32.f32 %0, %1;" : "=r"(r) : "f"(x));
    return r;
}
__device__ __forceinline__ void mma_tf32(float c[4],
    unsigned a0, unsigned a1, unsigned a2, unsigned a3, unsigned b0, unsigned b1)
{
    asm volatile("mma.sync.aligned.m16n8k8.row.col.f32.tf32.tf32.f32 "
        "{%0,%1,%2,%3}, {%4,%5,%6,%7}, {%8,%9}, {%0,%1,%2,%3};"
        : "+f"(c[0]), "+f"(c[1]), "+f"(c[2]), "+f"(c[3])
        : "r"(a0), "r"(a1), "r"(a2), "r"(a3), "r"(b0), "r"(b1));
}

// C[m,n] = sum_k A[m,k]*B[k,n]; 128x128 block tile, 8 warps (2m x 4n), BK=16.
__global__ void __launch_bounds__(256, 2) gemm_tf32_kernel(
    const float* __restrict__ Ag, const float* __restrict__ Bg,
    float* __restrict__ Cg, int M, int N, int K,
    int lda, int ldb, int ldc, long long sA, long long sB, long long sC)
{
    __shared__ unsigned As[16][132];   // [k][m], tf32 bits
    __shared__ unsigned Bs[16][132];   // [k][n]
    const int tid = threadIdx.x;
    const int wid = tid >> 5, lane = tid & 31;
    const int wm = wid >> 2, wn = wid & 3;        // 2 x 4 warp grid
    const int m_w = wm * 64, n_w = wn * 32;       // 64 x 32 warp tile
    const int g = lane >> 2, tg = lane & 3;
    const int m0 = blockIdx.y * 128, n0 = blockIdx.x * 128;
    const float* Ab = Ag + (long long)blockIdx.z * sA;
    const float* Bb = Bg + (long long)blockIdx.z * sB;
    float*       Cb = Cg + (long long)blockIdx.z * sC;

    float acc[4][4][4];
    #pragma unroll
    for (int i = 0; i < 4; i++)
        #pragma unroll
        for (int j = 0; j < 4; j++)
            #pragma unroll
            for (int q = 0; q < 4; q++) acc[i][j][q] = 0.f;

    const int a_c = (tid & 3) * 4;
    const int a_r = tid >> 2;
    const int bn_q = (tid & 31) * 4;
    const int bk_r = tid >> 5;

    for (int k0 = 0; k0 < K; k0 += 16) {
        const bool fullk = (k0 + 16 <= K);
        #pragma unroll
        for (int i = 0; i < 2; i++) {
            int m = a_r + 64*i;
            int gm = m0 + m;
            float4 v = make_float4(0.f,0.f,0.f,0.f);
            if (gm < M) {
                const float* p = Ab + (long long)gm*lda + k0 + a_c;
                if (fullk) v = *(const float4*)p;
                else {
                    if (k0 + a_c + 0 < K) v.x = p[0];
                    if (k0 + a_c + 1 < K) v.y = p[1];
                    if (k0 + a_c + 2 < K) v.z = p[2];
                    if (k0 + a_c + 3 < K) v.w = p[3];
                }
            }
            As[a_c+0][m] = f2tf32(v.x); As[a_c+1][m] = f2tf32(v.y);
            As[a_c+2][m] = f2tf32(v.z); As[a_c+3][m] = f2tf32(v.w);
        }
        #pragma unroll
        for (int i = 0; i < 2; i++) {
            int k = bk_r + 8*i;
            int gk = k0 + k;
            int gn = n0 + bn_q;
            float4 v = make_float4(0.f,0.f,0.f,0.f);
            if (gk < K) {
                const float* p = Bb + (long long)gk*ldb + gn;
                if (gn + 3 < N) v = *(const float4*)p;
                else {
                    if (gn+0 < N) v.x = p[0];
                    if (gn+1 < N) v.y = p[1];
                    if (gn+2 < N) v.z = p[2];
                }
            }
            Bs[k][bn_q+0] = f2tf32(v.x); Bs[k][bn_q+1] = f2tf32(v.y);
            Bs[k][bn_q+2] = f2tf32(v.z); Bs[k][bn_q+3] = f2tf32(v.w);
        }
        __syncthreads();
        #pragma unroll
        for (int kk = 0; kk < 16; kk += 8) {
            unsigned bfr[4][2];
            #pragma unroll
            for (int nt = 0; nt < 4; nt++) {
                int n = n_w + nt*8 + g;
                bfr[nt][0] = Bs[kk + tg][n];
                bfr[nt][1] = Bs[kk + tg + 4][n];
            }
            #pragma unroll
            for (int mt = 0; mt < 4; mt++) {
                int m = m_w + mt*16 + g;
                unsigned a0 = As[kk + tg][m];
                unsigned a1 = As[kk + tg][m + 8];
                unsigned a2 = As[kk + tg + 4][m];
                unsigned a3 = As[kk + tg + 4][m + 8];
                #pragma unroll
                for (int nt = 0; nt < 4; nt++)
                    mma_tf32(acc[mt][nt], a0, a1, a2, a3, bfr[nt][0], bfr[nt][1]);
            }
        }
        __syncthreads();
    }
    #pragma unroll
    for (int mt = 0; mt < 4; mt++) {
        #pragma unroll
        for (int nt = 0; nt < 4; nt++) {
            int r0 = m0 + m_w + mt*16 + g;
            int r1 = r0 + 8;
            int c  = n0 + n_w + nt*8 + 2*tg;
            if (r0 < M) {
                if (c   < N) Cb[(long long)r0*ldc + c]   = acc[mt][nt][0];
                if (c+1 < N) Cb[(long long)r0*ldc + c+1] = acc[mt][nt][1];
            }
            if (r1 < M) {
                if (c   < N) Cb[(long long)r1*ldc + c]   = acc[mt][nt][2];
                if (c+1 < N) Cb[(long long)r1*ldc + c+1] = acc[mt][nt][3];
            }
        }
    }
}

// ---------------- masked softmax -> Am (d_out) + AmP (padded) ----------------
__global__ void softmax_kernel(float* __restrict__ Am)
{
    int row = blockIdx.x;                    // b*L + l
    const float* Ar = g_A  + (size_t)row * LL;
    const float* Tr = g_Ti + (size_t)row * LL;
    int t = threadIdx.x;
    const float scale = 0.07142857142857142f;
    float v[4], mb[4];
    float mx = -INFINITY;
    #pragma unroll
    for (int i = 0; i < 4; i++) {
        int m = t + i*NTHREADS;
        v[i] = 0.f; mb[i] = 0.f;
        if (m < LL) {
            float mask = sigmoid_ref(Tr[m]);
            v[i] = Ar[m] * mask * scale;
            mb[i] = (mask != 0.f) ? 1.f : 0.f;
            mx = fmaxf(mx, v[i]);
        }
    }
    __shared__ float red[NTHREADS];
    red[t] = mx; __syncthreads();
    for (int s = NTHREADS/2; s > 0; s >>= 1) {
        if (t < s) red[t] = fmaxf(red[t], red[t+s]);
        __syncthreads();
    }
    mx = red[0]; __syncthreads();
    float e[4]; float sum = 0.f;
    #pragma unroll
    for (int i = 0; i < 4; i++) {
        int m = t + i*NTHREADS;
        if (m < LL) { e[i] = expf(v[i] - mx); sum += e[i]; } else e[i] = 0.f;
    }
    red[t] = sum; __syncthreads();
    for (int s = NTHREADS/2; s > 0; s >>= 1) {
        if (t < s) red[t] += red[t+s];
        __syncthreads();
    }
    float inv = 1.f / red[0];
    #pragma unroll
    for (int i = 0; i < 4; i++) {
        int m = t + i*NTHREADS;
        if (m < LL) {
            float val = e[i] * inv * mb[i];
            Am[(size_t)row*LL + m] = val;
            g_AmP[(size_t)row*LLP + m] = val;
        }
    }
}

// ---------------- fold (gather form, no atomics) ------------------------------
__global__ void fold_kernel()
{
    size_t t = (size_t)blockIdx.x * NTHREADS + threadIdx.x;
    if (t >= (size_t)B_*CIN*Hh*Ww) return;
    int w = (int)(t % Ww); size_t r = t / Ww;
    int h = (int)(r % Hh); r /= Hh;
    int c = (int)(r % CIN);
    int b = (int)(r / CIN);
    int i0 = (h > 6) ? (h - 3) >> 2 : 0;
    int i1 = h >> 2; if (i1 > NHH - 1) i1 = NHH - 1;
    int j0 = (w > 6) ? (w - 3) >> 2 : 0;
    int j1 = w >> 2; if (j1 > NHH - 1) j1 = NHH - 1;
    float s = 0.f;
    for (int i = i0; i <= i1; i++) {
        int kh = h - i*4;
        for (int j = j0; j <= j1; j++) {
            int kw = w - j*4;
            s += g_y[((size_t)b*LL + i*NHH + j)*FV + c*49 + kh*7 + kw];
        }
    }
    g_fold[t] = s;
}

// ---------------- conv c1: refpad 3x3, 32->16, leaky(0.2) --------------------
__global__ void conv3x3_c1_kernel(const float* __restrict__ w1)
{
    __shared__ float sw[CI*CIN*9];
    int t = threadIdx.x;
    for (int i = t; i < CI*CIN*9; i += NTHREADS) sw[i] = w1[i];
    __syncthreads();
    int pix = blockIdx.x * NTHREADS + t;
    int b = blockIdx.y;
    int h = pix >> 7, w = pix & 127;
    float acc[CI];
    #pragma unroll
    for (int co = 0; co < CI; co++) acc[co] = 0.f;
    const float* xb = g_fold + (size_t)b * CIN * Hh * Ww;
    for (int ci = 0; ci < CIN; ci++) {
        float v[9];
        #pragma unroll
        for (int dh = 0; dh < 3; dh++) {
            int hh = h + dh - 1;
            hh = hh < 0 ? 1 : (hh >= Hh ? Hh - 2 : hh);
            #pragma unroll
            for (int dw = 0; dw < 3; dw++) {
                int w2p = w + dw - 1;
                w2p = w2p < 0 ? 1 : (w2p >= Ww ? Ww - 2 : w2p);
                v[dh*3 + dw] = xb[(ci*Hh + hh)*Ww + w2p];
            }
        }
        #pragma unroll
        for (int co = 0; co < CI; co++) {
            const float* p1 = &sw[(co*CIN + ci)*9];
            float s1 = 0.f;
            #pragma unroll
            for (int k = 0; k < 9; k++) s1 += p1[k]*v[k];
            acc[co] += s1;
        }
    }
    size_t base = (size_t)b * CI * Hh * Ww + pix;
    #pragma unroll
    for (int co = 0; co < CI; co++) {
        float s = acc[co];
        g_o1[base + (size_t)co*Hh*Ww] = (s > 0.f) ? s : 0.2f*s;
    }
}

// ---------------- conv c2: 1x1 16->32, leaky(0.2), + residual ----------------
__global__ void conv1x1_c2_res_kernel(const float* __restrict__ cw,
                                      const float* __restrict__ x,
                                      float* __restrict__ outp)
{
    __shared__ float sw[CIN*CI];
    int t = threadIdx.x;
    for (int i = t; i < CIN*CI; i += NTHREADS) sw[i] = cw[i];
    __syncthreads();
    int pix = blockIdx.x * NTHREADS + t;
    int b = blockIdx.y;
    float in[CI];
    #pragma unroll
    for (int ci = 0; ci < CI; ci++) in[ci] = g_o1[((size_t)b*CI + ci)*Hh*Ww + pix];
    #pragma unroll
    for (int co = 0; co < CIN; co++) {
        float s = 0.f;
        #pragma unroll
        for (int ci = 0; ci < CI; ci++) s += sw[co*CI + ci]*in[ci];
        s = (s > 0.f) ? s : 0.2f*s;
        size_t idx = ((size_t)b*CIN + co)*Hh*Ww + pix;
        outp[idx] = x[idx] + s;
    }
}

// ---------------- launch ------------------------------------------------------
extern "C" void kernel_launch(void* const* d_in, const int* in_sizes, int n_in,
                              void* d_out, int out_size)
{
    const float* x        = (const float*)d_in[0];
    const float* g_w      = (const float*)d_in[1];
    const float* g_b      = (const float*)d_in[2];
    const float* w_w      = (const float*)d_in[3];
    const float* w_b      = (const float*)d_in[4];
    const float* theta_w  = (const float*)d_in[5];
    const float* theta_b  = (const float*)d_in[6];
    const float* fc1_w    = (const float*)d_in[7];
    const float* fc1_b    = (const float*)d_in[8];
    const float* mconv_w  = (const float*)d_in[9];
    const float* mconv_b  = (const float*)d_in[10];
    const float* mfc_w    = (const float*)d_in[11];
    const float* mfc_b    = (const float*)d_in[12];
    const float* c1_w     = (const float*)d_in[13];
    const float* c2_w     = (const float*)d_in[14];
    float* out = (float*)d_out;

    float *px1, *px2, *px3, *pp6, *pp4, *pp62, *pwf, *pxf, *pA, *pTi, *pW2,
          *pMsumP, *pbsum, *pAmP, *py;
    cudaGetSymbolAddress((void**)&px1,   g_x1);
    cudaGetSymbolAddress((void**)&px2,   g_x2);
    cudaGetSymbolAddress((void**)&px3,   g_x3);
    cudaGetSymbolAddress((void**)&pp6,   g_p6);
    cudaGetSymbolAddress((void**)&pp4,   g_p4);
    cudaGetSymbolAddress((void**)&pp62,  g_p62);
    cudaGetSymbolAddress((void**)&pwf,   g_wf);
    cudaGetSymbolAddress((void**)&pxf,   g_xf);
    cudaGetSymbolAddress((void**)&pA,    g_A);
    cudaGetSymbolAddress((void**)&pTi,   g_Ti);
    cudaGetSymbolAddress((void**)&pW2,   g_W2);
    cudaGetSymbolAddress((void**)&pMsumP,g_MsumP);
    cudaGetSymbolAddress((void**)&pbsum, g_bsum);
    cudaGetSymbolAddress((void**)&pAmP,  g_AmP);
    cudaGetSymbolAddress((void**)&py,    g_y);

    dim3 convGrid(Hh*Ww/NTHREADS, B_);

    conv3x3_dual_kernel<<<convGrid, NTHREADS>>>(x, g_w, g_b, w_w, w_b);
    conv1x1_theta_kernel<<<convGrid, NTHREADS>>>(theta_w, theta_b);

    {
        size_t tot = (size_t)B_*LL*FIN;
        int nb = (int)((tot + NTHREADS - 1) / NTHREADS);
        unfold_kernel<<<nb, NTHREADS>>>(px1, pp6,  CI, tot);
        unfold_kernel<<<nb, NTHREADS>>>(px2, pp4,  CI, tot);
    }
    {
        size_t tot = (size_t)B_*LL*FV;
        int nb = (int)((tot + NTHREADS - 1) / NTHREADS);
        unfold_kernel<<<nb, NTHREADS>>>(px3, pp62, CIN, tot);
    }

    msum_kernel<<<(int)(((size_t)LL*LL + NTHREADS - 1)/NTHREADS), NTHREADS>>>(
        mconv_w, mfc_w, mconv_b, mfc_b);

    // wf = p4 @ fc1_w^T + fc1_b ; xf = p6 @ fc1_w^T + fc1_b  (flat M = B*L)
    {
        dim3 g((FOUT + 127)/128, (B_*LL + 127)/128, 1);
        gemm128_kernel<true><<<g, 256>>>(pp4, fc1_w, pwf, B_*LL, FOUT, FIN,
                                         FIN, FIN, FOUT, 0, 0, 0, nullptr, fc1_b);
        gemm128_kernel<true><<<g, 256>>>(pp6, fc1_w, pxf, B_*LL, FOUT, FIN,
                                         FIN, FIN, FOUT, 0, 0, 0, nullptr, fc1_b);
    }
    // A[b] = wf[b] @ xf[b]^T
    {
        dim3 g((LL + 127)/128, (LL + 127)/128, B_);
        gemm128_kernel<true><<<g, 256>>>(pwf, pxf, pA, LL, LL, FOUT,
                                         FOUT, FOUT, LL,
                                         (long long)LL*FOUT, (long long)LL*FOUT,
                                         (long long)LL*LL, nullptr, nullptr);
    }
    // W2[b] = Msum @ wf[b]   (assoc. rewrite of Ti = Msum @ A)
    {
        dim3 g((FOUT + 127)/128, (LL + 127)/128, B_);
        gemm128_kernel<false><<<g, 256>>>(pMsumP, pwf, pW2, LL, FOUT, LL,
                                          LLP, FOUT, FOUT,
                                          0, (long long)LL*FOUT, (long long)LL*FOUT,
                                          nullptr, nullptr);
    }
    // Ti[b] = W2[b] @ xf[b]^T + bsum (row bias)
    {
        dim3 g((LL + 127)/128, (LL + 127)/128, B_);
        gemm128_kernel<true><<<g, 256>>>(pW2, pxf, pTi, LL, LL, FOUT,
                                         FOUT, FOUT, LL,
                                         (long long)LL*FOUT, (long long)LL*FOUT,
                                         (long long)LL*LL, pbsum, nullptr);
    }

    softmax_kernel<<<B_*LL, NTHREADS>>>(out);

    // y[b] = Am[b] @ p62[b]  (TF32 tensor cores)
    {
        dim3 g((FV + 127)/128, (LL + 127)/128, B_);
        gemm_tf32_kernel<<<g, 256>>>(pAmP, pp62, py, LL, FV, LL,
                                     LLP, FV, FV,
                                     (long long)LL*LLP, (long long)LL*FV,
                                     (long long)LL*FV);
    }

    fold_kernel<<<(int)(((size_t)B_*CIN*Hh*Ww + NTHREADS - 1)/NTHREADS), NTHREADS>>>();
    conv3x3_c1_kernel<<<convGrid, NTHREADS>>>(c1_w);
    conv1x1_c2_res_kernel<<<convGrid, NTHREADS>>>(c2_w, x, out + (size_t)B_*LL*LL);
}